// round 5
// baseline (speedup 1.0000x reference)
#include <cuda_runtime.h>
#include <cstdint>

#define NROWS 8192
#define L2E 1.44269504088896340736f

// ---------------- scratch ----------------
__device__ __align__(16) unsigned g_mask[NROWS * 256];   // 8 MB bitmask
__device__ __align__(16) float g_h[4 * NROWS * 64];      // per-head h = x@Wh
__device__ __align__(16) float g_xcat[NROWS * 256];      // concat LR(head outputs)
__device__ __align__(16) float g_h2[NROWS * 16];         // xcat@Wo
__device__ __align__(16) float g_f1[5 * NROWS];          // f1 * log2e per layer
__device__ __align__(16) float g_f2[5 * NROWS];          // f2 * log2e per layer
__device__ __align__(16) float4 g_fb4[5 * NROWS];        // {f2, 2^f2, 2^(0.2 f2), 0}
__device__ __align__(16) float2 g_a[5 * NROWS];          // {2^(f1-m), 2^(0.2 f1 - m)}
__device__ __align__(16) float g_part[8 * NROWS * 16];   // final-layer partials
__device__ __align__(16) float g_partZ[8 * NROWS];

// ---------------- helpers ----------------
__device__ __forceinline__ float ex2f(float x) {
    float r; asm("ex2.approx.ftz.f32 %0, %1;" : "=f"(r) : "f"(x)); return r;
}
__device__ __forceinline__ unsigned long long pk2(float a, float b) {
    unsigned long long r; asm("mov.b64 %0, {%1, %2};" : "=l"(r) : "f"(a), "f"(b)); return r;
}
__device__ __forceinline__ void up2(unsigned long long v, float& a, float& b) {
    asm("mov.b64 {%0, %1}, %2;" : "=f"(a), "=f"(b) : "l"(v));
}
__device__ __forceinline__ void fma2(unsigned long long& d, unsigned long long a, unsigned long long b) {
    asm("fma.rn.f32x2 %0, %1, %2, %0;" : "+l"(d) : "l"(a), "l"(b));
}
__device__ __forceinline__ void lds2u64(const float* p, unsigned long long& a, unsigned long long& b) {
    unsigned sa = (unsigned)__cvta_generic_to_shared(p);
    asm volatile("ld.shared.v2.u64 {%0, %1}, [%2];" : "=l"(a), "=l"(b) : "r"(sa));
}

// ---------------- 1) pack adjacency ----------------
__global__ void __launch_bounds__(256) pack_adj_kernel(const int* __restrict__ adj) {
    const int lane = threadIdx.x & 31;
    const int wid = (blockIdx.x * blockDim.x + threadIdx.x) >> 5;
    const int nWarps = (gridDim.x * blockDim.x) >> 5;
    for (int w = wid; w < NROWS * 256; w += nWarps) {
        int v = adj[(size_t)w * 32 + lane];
        unsigned b = __ballot_sync(0xffffffffu, v > 0);
        if (lane == 0) g_mask[w] = b;
    }
}

// ---------------- 2) h = x @ Wh[head] (8192x512x64) ----------------
__global__ void __launch_bounds__(256) gemm64_kernel(const float* __restrict__ X,
                                                     const float* __restrict__ WhAll) {
    const int head = blockIdx.y;
    const float* W = WhAll + head * (512 * 64);
    float* C = g_h + head * (NROWS * 64);
    const int r0 = blockIdx.x * 64;
    const int tid = threadIdx.x;
    __shared__ float4 As4[512];  // [32 k][64 m]
    __shared__ float4 Bs4[512];  // [32 k][64 n]
    float* As = (float*)As4;
    const int tr = tid >> 4, tc = tid & 15;
    const int lm = tid & 63, kg = tid >> 6;
    float acc[4][4];
#pragma unroll
    for (int i = 0; i < 4; i++)
#pragma unroll
        for (int j = 0; j < 4; j++) acc[i][j] = 0.f;

    for (int kt = 0; kt < 512; kt += 32) {
        __syncthreads();
        const float* xb = X + (size_t)(r0 + lm) * 512 + kt + kg * 8;
        float4 a0 = ((const float4*)xb)[0];
        float4 a1 = ((const float4*)xb)[1];
        As[(kg * 8 + 0) * 64 + lm] = a0.x; As[(kg * 8 + 1) * 64 + lm] = a0.y;
        As[(kg * 8 + 2) * 64 + lm] = a0.z; As[(kg * 8 + 3) * 64 + lm] = a0.w;
        As[(kg * 8 + 4) * 64 + lm] = a1.x; As[(kg * 8 + 5) * 64 + lm] = a1.y;
        As[(kg * 8 + 6) * 64 + lm] = a1.z; As[(kg * 8 + 7) * 64 + lm] = a1.w;
        const float4* wsrc = (const float4*)(W + kt * 64);
        Bs4[tid] = wsrc[tid];
        Bs4[tid + 256] = wsrc[tid + 256];
        __syncthreads();
#pragma unroll
        for (int kk = 0; kk < 32; kk++) {
            float4 av = As4[kk * 16 + tr];
            float4 bv = Bs4[kk * 16 + tc];
            float aa[4] = {av.x, av.y, av.z, av.w};
            float bb[4] = {bv.x, bv.y, bv.z, bv.w};
#pragma unroll
            for (int i = 0; i < 4; i++)
#pragma unroll
                for (int j = 0; j < 4; j++) acc[i][j] += aa[i] * bb[j];
        }
    }
#pragma unroll
    for (int i = 0; i < 4; i++) {
        float4 o = make_float4(acc[i][0], acc[i][1], acc[i][2], acc[i][3]);
        *(float4*)(C + (size_t)(r0 + tr * 4 + i) * 64 + tc * 4) = o;
    }
}

// ---------------- 3) f1/f2 (log2-scaled) ----------------
__global__ void __launch_bounds__(256) f1f2_heads_kernel(const float* __restrict__ ah) {
    const int head = blockIdx.y;
    const float* H = g_h + head * (NROWS * 64);
    const float* a = ah + head * 128;
    const int lane = threadIdx.x & 31;
    const int row = blockIdx.x * 8 + (threadIdx.x >> 5);
    float h0 = H[row * 64 + lane], h1 = H[row * 64 + 32 + lane];
    float s1 = h0 * a[lane] + h1 * a[32 + lane];
    float s2 = h0 * a[64 + lane] + h1 * a[96 + lane];
#pragma unroll
    for (int off = 16; off; off >>= 1) {
        s1 += __shfl_xor_sync(0xffffffffu, s1, off);
        s2 += __shfl_xor_sync(0xffffffffu, s2, off);
    }
    if (lane == 0) {
        g_f1[head * NROWS + row] = s1 * L2E;
        g_f2[head * NROWS + row] = s2 * L2E;
    }
}

__global__ void __launch_bounds__(256) f1f2_final_kernel(const float* __restrict__ ao) {
    const int lane = threadIdx.x & 31;
    const int row = blockIdx.x * 8 + (threadIdx.x >> 5);
    float s1 = 0.f, s2 = 0.f;
    if (lane < 16) {
        float h = g_h2[row * 16 + lane];
        s1 = h * ao[lane];
        s2 = h * ao[16 + lane];
    }
#pragma unroll
    for (int off = 16; off; off >>= 1) {
        s1 += __shfl_xor_sync(0xffffffffu, s1, off);
        s2 += __shfl_xor_sync(0xffffffffu, s2, off);
    }
    if (lane == 0) {
        g_f1[4 * NROWS + row] = s1 * L2E;
        g_f2[4 * NROWS + row] = s2 * L2E;
    }
}

// ---------------- 3b) B values: {f2, 2^f2, 2^(0.2 f2)} per column ----------------
__global__ void __launch_bounds__(256) bvals_kernel(int layer0) {
    const int layer = layer0 + blockIdx.y;
    const int j = blockIdx.x * 256 + threadIdx.x;
    float f2 = g_f2[layer * NROWS + j];
    g_fb4[layer * NROWS + j] = make_float4(f2, ex2f(f2), ex2f(0.2f * f2), 0.f);
}

// ---------------- 4a) masked row max + A values, ALL 4 HEADS in one mask pass ----
__global__ void __launch_bounds__(256) rowmax4_kernel() {
    const int lane = threadIdx.x & 31;
    const int row = blockIdx.x * 8 + (threadIdx.x >> 5);
    const int sh = (lane & 7) * 4;
    float mx0 = -3.0e38f, mx1 = -3.0e38f, mx2 = -3.0e38f, mx3 = -3.0e38f;
    for (int jb = 0; jb < NROWS; jb += 128) {
        uint4 mw = *(const uint4*)&g_mask[row * 256 + (jb >> 5)];
        unsigned word = (lane < 8) ? mw.x : (lane < 16) ? mw.y : (lane < 24) ? mw.z : mw.w;
        const int j = jb + lane * 4;
        float4 v0 = *(const float4*)&g_f2[0 * NROWS + j];
        float4 v1 = *(const float4*)&g_f2[1 * NROWS + j];
        float4 v2 = *(const float4*)&g_f2[2 * NROWS + j];
        float4 v3 = *(const float4*)&g_f2[3 * NROWS + j];
#pragma unroll
        for (int i = 0; i < 4; i++) {
            bool on = (word >> (sh + i)) & 1u;
            mx0 = fmaxf(mx0, on ? ((const float*)&v0)[i] : -3.0e38f);
            mx1 = fmaxf(mx1, on ? ((const float*)&v1)[i] : -3.0e38f);
            mx2 = fmaxf(mx2, on ? ((const float*)&v2)[i] : -3.0e38f);
            mx3 = fmaxf(mx3, on ? ((const float*)&v3)[i] : -3.0e38f);
        }
    }
#pragma unroll
    for (int off = 16; off; off >>= 1) {
        mx0 = fmaxf(mx0, __shfl_xor_sync(0xffffffffu, mx0, off));
        mx1 = fmaxf(mx1, __shfl_xor_sync(0xffffffffu, mx1, off));
        mx2 = fmaxf(mx2, __shfl_xor_sync(0xffffffffu, mx2, off));
        mx3 = fmaxf(mx3, __shfl_xor_sync(0xffffffffu, mx3, off));
    }
    if (lane == 0) {
        float mx[4] = {mx0, mx1, mx2, mx3};
#pragma unroll
        for (int hd = 0; hd < 4; hd++) {
            float f1v = g_f1[hd * NROWS + row];
            float s = f1v + mx[hd];
            float m = fmaxf(s, 0.2f * s);
            g_a[hd * NROWS + row] = make_float2(ex2f(f1v - m), ex2f(0.2f * f1v - m));
        }
    }
}

// ---------------- 4b) masked row max + A values, final layer ----------------
__global__ void __launch_bounds__(256) rowmax1_kernel() {
    const int lane = threadIdx.x & 31;
    const int row = blockIdx.x * 8 + (threadIdx.x >> 5);
    const int sh = (lane & 7) * 4;
    const float* __restrict__ f2 = g_f2 + 4 * NROWS;
    float mx = -3.0e38f;
    for (int jb = 0; jb < NROWS; jb += 128) {
        uint4 mw = *(const uint4*)&g_mask[row * 256 + (jb >> 5)];
        unsigned word = (lane < 8) ? mw.x : (lane < 16) ? mw.y : (lane < 24) ? mw.z : mw.w;
        float4 v = *(const float4*)&f2[jb + lane * 4];
#pragma unroll
        for (int i = 0; i < 4; i++) {
            bool on = (word >> (sh + i)) & 1u;
            mx = fmaxf(mx, on ? ((const float*)&v)[i] : -3.0e38f);
        }
    }
#pragma unroll
    for (int off = 16; off; off >>= 1) mx = fmaxf(mx, __shfl_xor_sync(0xffffffffu, mx, off));
    if (lane == 0) {
        float f1v = g_f1[4 * NROWS + row];
        float s = f1v + mx;
        float m = fmaxf(s, 0.2f * s);
        g_a[4 * NROWS + row] = make_float2(ex2f(f1v - m), ex2f(0.2f * f1v - m));
    }
}

// ---------------- 5) head attention -> xcat (2 threads per row, NO exp in loop) ----
__global__ void __launch_bounds__(256) attn_heads_kernel() {
    const int head = blockIdx.y;
    const float* __restrict__ H = g_h + head * (NROWS * 64);
    const int r0 = blockIdx.x * 128;
    const int tid = threadIdx.x;
    const int rowLocal = tid >> 1;
    const int c0 = (tid & 1) * 32;
    __shared__ float4 Hs4[2048];  // 128x64 f32
    __shared__ float4 fbs[128];   // {f2, B+, B-, 0}
    __shared__ uint4 ms4[128];
    float* Hs = (float*)Hs4;
    unsigned* msw = (unsigned*)ms4;
    const int row = r0 + rowLocal;
    const float f1i = g_f1[head * NROWS + row];
    const float2 av = g_a[head * NROWS + row];
    const float Ap = av.x, Am = av.y;
    unsigned long long acc[16];
#pragma unroll
    for (int q = 0; q < 16; q++) acc[q] = 0ull;
    float z = 0.f;

    for (int j0 = 0; j0 < NROWS; j0 += 128) {
        __syncthreads();
        const float4* src = (const float4*)(H + (size_t)j0 * 64);
#pragma unroll
        for (int v = 0; v < 8; v++) Hs4[tid + 256 * v] = src[tid + 256 * v];
        if (tid < 128) fbs[tid] = g_fb4[head * NROWS + j0 + tid];
        const int wb = j0 >> 5;
#pragma unroll
        for (int v = 0; v < 2; v++) {
            int idx = tid + 256 * v;
            msw[idx] = g_mask[(size_t)(r0 + (idx >> 2)) * 256 + wb + (idx & 3)];
        }
        __syncthreads();
        uint4 mwv = ms4[rowLocal];
        unsigned bw[4] = {mwv.x, mwv.y, mwv.z, mwv.w};
#pragma unroll
        for (int w = 0; w < 4; w++) {
            unsigned bits = bw[w];
#pragma unroll 4
            for (int t = 0; t < 32; t++) {
                const int jj = w * 32 + t;
                float4 fb = fbs[jj];
                float s = f1i + fb.x;
                bool pos = s >= 0.f;
                float b = pos ? fb.y : fb.z;
                float a = pos ? Ap : Am;
                float p = ((bits >> t) & 1u) ? a * b : 0.f;
                z += p;
                unsigned long long p2 = pk2(p, p);
                const float* hp = Hs + jj * 64 + c0;
#pragma unroll
                for (int q = 0; q < 8; q++) {
                    unsigned long long h0, h1;
                    lds2u64(hp + q * 4, h0, h1);
                    fma2(acc[2 * q], p2, h0);
                    fma2(acc[2 * q + 1], p2, h1);
                }
            }
        }
    }
    float inv = 1.f / z;
    float* outp = g_xcat + (size_t)row * 256 + head * 64 + c0;
#pragma unroll
    for (int q = 0; q < 16; q++) {
        float a, b;
        up2(acc[q], a, b);
        a *= inv; b *= inv;
        a = fmaxf(a, 0.01f * a);
        b = fmaxf(b, 0.01f * b);
        outp[2 * q] = a;
        outp[2 * q + 1] = b;
    }
}

// ---------------- 6) h2 = xcat @ Wo (8192x256x16) ----------------
__global__ void __launch_bounds__(128) gemm2_kernel(const float* __restrict__ Wo) {
    __shared__ float Ws[256 * 16];
    const int tid = threadIdx.x;
    for (int i = tid; i < 4096; i += 128) Ws[i] = Wo[i];
    __syncthreads();
    const int row = blockIdx.x * 128 + tid;
    const float* xr = g_xcat + (size_t)row * 256;
    float acc[16];
#pragma unroll
    for (int j = 0; j < 16; j++) acc[j] = 0.f;
    for (int k = 0; k < 256; k += 4) {
        float4 xv = *(const float4*)(xr + k);
#pragma unroll
        for (int j = 0; j < 16; j++) {
            acc[j] += xv.x * Ws[(k + 0) * 16 + j];
            acc[j] += xv.y * Ws[(k + 1) * 16 + j];
            acc[j] += xv.z * Ws[(k + 2) * 16 + j];
            acc[j] += xv.w * Ws[(k + 3) * 16 + j];
        }
    }
#pragma unroll
    for (int j = 0; j < 16; j++) g_h2[row * 16 + j] = acc[j];
}

// ---------------- 7) final attention (j-split partials, NO exp in loop) ----------
__global__ void __launch_bounds__(128) attn_final_kernel() {
    const int chunk = blockIdx.y;  // 0..7, each 1024 j
    const int r0 = blockIdx.x * 128;
    const int tid = threadIdx.x;
    __shared__ float4 Hs4[512];  // 128x16 f32
    __shared__ float4 fbs[128];
    __shared__ uint4 ms4[128];
    float* Hs = (float*)Hs4;
    unsigned* msw = (unsigned*)ms4;
    const int row = r0 + tid;
    const float f1i = g_f1[4 * NROWS + row];
    const float2 avv = g_a[4 * NROWS + row];
    const float Ap = avv.x, Am = avv.y;
    unsigned long long acc[8];
#pragma unroll
    for (int q = 0; q < 8; q++) acc[q] = 0ull;
    float z = 0.f;

    for (int j0 = chunk * 1024; j0 < chunk * 1024 + 1024; j0 += 128) {
        __syncthreads();
        const float4* src = (const float4*)(g_h2 + (size_t)j0 * 16);
#pragma unroll
        for (int v = 0; v < 4; v++) Hs4[tid + 128 * v] = src[tid + 128 * v];
        fbs[tid] = g_fb4[4 * NROWS + j0 + tid];
        const int wb = j0 >> 5;
#pragma unroll
        for (int v = 0; v < 4; v++) {
            int idx = tid + 128 * v;
            msw[idx] = g_mask[(size_t)(r0 + (idx >> 2)) * 256 + wb + (idx & 3)];
        }
        __syncthreads();
        uint4 mwv = ms4[tid];
        unsigned bw[4] = {mwv.x, mwv.y, mwv.z, mwv.w};
#pragma unroll
        for (int w = 0; w < 4; w++) {
            unsigned bits = bw[w];
#pragma unroll 4
            for (int t = 0; t < 32; t++) {
                const int jj = w * 32 + t;
                float4 fb = fbs[jj];
                float s = f1i + fb.x;
                bool pos = s >= 0.f;
                float b = pos ? fb.y : fb.z;
                float a = pos ? Ap : Am;
                float p = ((bits >> t) & 1u) ? a * b : 0.f;
                z += p;
                unsigned long long p2 = pk2(p, p);
                const float* hp = Hs + jj * 16;
#pragma unroll
                for (int q = 0; q < 4; q++) {
                    unsigned long long h0, h1;
                    lds2u64(hp + q * 4, h0, h1);
                    fma2(acc[2 * q], p2, h0);
                    fma2(acc[2 * q + 1], p2, h1);
                }
            }
        }
    }
    float* pp = g_part + ((size_t)chunk * NROWS + row) * 16;
#pragma unroll
    for (int q = 0; q < 8; q++) {
        float a, b;
        up2(acc[q], a, b);
        pp[2 * q] = a;
        pp[2 * q + 1] = b;
    }
    g_partZ[chunk * NROWS + row] = z;
}

// ---------------- 8) reduce partials -> output ----------------
__global__ void __launch_bounds__(256) reduce_kernel(float* __restrict__ out) {
    const int idx = blockIdx.x * 256 + threadIdx.x;  // 8192*16
    const int row = idx >> 4;
    float s = 0.f, z = 0.f;
#pragma unroll
    for (int c = 0; c < 8; c++) {
        s += g_part[((size_t)c * NROWS + row) * 16 + (idx & 15)];
        z += g_partZ[c * NROWS + row];
    }
    out[idx] = s / z;
}

extern "C" void kernel_launch(void* const* d_in, const int* in_sizes, int n_in,
                              void* d_out, int out_size) {
    const float* x   = (const float*)d_in[0];
    const int*   adj = (const int*)d_in[1];
    const float* Wh  = (const float*)d_in[2];
    const float* ah  = (const float*)d_in[3];
    const float* Wo  = (const float*)d_in[4];
    const float* ao  = (const float*)d_in[5];
    float* out = (float*)d_out;

    pack_adj_kernel<<<2048, 256>>>(adj);
    gemm64_kernel<<<dim3(128, 4), 256>>>(x, Wh);
    f1f2_heads_kernel<<<dim3(1024, 4), 256>>>(ah);
    bvals_kernel<<<dim3(32, 4), 256>>>(0);
    rowmax4_kernel<<<1024, 256>>>();
    attn_heads_kernel<<<dim3(64, 4), 256>>>();
    gemm2_kernel<<<64, 128>>>(Wo);
    f1f2_final_kernel<<<1024, 256>>>(ao);
    bvals_kernel<<<dim3(32, 1), 256>>>(4);
    rowmax1_kernel<<<1024, 256>>>();
    attn_final_kernel<<<dim3(64, 8), 128>>>();
    reduce_kernel<<<512, 256>>>(out);
}

// round 6
// speedup vs baseline: 2.1038x; 2.1038x over previous
#include <cuda_runtime.h>
#include <cstdint>

#define NROWS 8192
#define L2E 1.44269504088896340736f

// ---------------- scratch ----------------
__device__ __align__(16) unsigned g_mask[NROWS * 256];   // 8 MB bitmask
__device__ __align__(16) float g_h[4 * NROWS * 64];      // per-head h = x@Wh
__device__ __align__(16) float g_xcat[NROWS * 256];      // concat LR(head outputs)
__device__ __align__(16) float g_h2[NROWS * 16];         // xcat@Wo
__device__ __align__(16) float g_f1[5 * NROWS];          // f1 * log2e per layer
__device__ __align__(16) float g_f2[5 * NROWS];          // f2 * log2e per layer
__device__ __align__(16) float4 g_fb4[5 * NROWS];        // {f2, 2^f2, 2^(0.2 f2), 0}
__device__ __align__(16) float2 g_a[5 * NROWS];          // {2^(f1-m), 2^(0.2 f1 - m)}
__device__ __align__(16) float g_hp[16 * NROWS * 64];    // heads partials [split*4+head][row][64]
__device__ __align__(16) float g_hpZ[16 * NROWS];
__device__ __align__(16) float g_part[8 * NROWS * 16];   // final-layer partials
__device__ __align__(16) float g_partZ[8 * NROWS];

// ---------------- helpers ----------------
__device__ __forceinline__ float ex2f(float x) {
    float r; asm("ex2.approx.ftz.f32 %0, %1;" : "=f"(r) : "f"(x)); return r;
}
__device__ __forceinline__ unsigned long long pk2(float a, float b) {
    unsigned long long r; asm("mov.b64 %0, {%1, %2};" : "=l"(r) : "f"(a), "f"(b)); return r;
}
__device__ __forceinline__ void up2(unsigned long long v, float& a, float& b) {
    asm("mov.b64 {%0, %1}, %2;" : "=f"(a), "=f"(b) : "l"(v));
}
__device__ __forceinline__ void fma2(unsigned long long& d, unsigned long long a, unsigned long long b) {
    asm("fma.rn.f32x2 %0, %1, %2, %0;" : "+l"(d) : "l"(a), "l"(b));
}
__device__ __forceinline__ void lds2u64(const float* p, unsigned long long& a, unsigned long long& b) {
    unsigned sa = (unsigned)__cvta_generic_to_shared(p);
    asm volatile("ld.shared.v2.u64 {%0, %1}, [%2];" : "=l"(a), "=l"(b) : "r"(sa));
}
__device__ __forceinline__ unsigned long long lds1u64(const float* p) {
    unsigned sa = (unsigned)__cvta_generic_to_shared(p);
    unsigned long long r;
    asm volatile("ld.shared.b64 %0, [%1];" : "=l"(r) : "r"(sa));
    return r;
}

// ---------------- 1) pack adjacency ----------------
__global__ void __launch_bounds__(256) pack_adj_kernel(const int* __restrict__ adj) {
    const int lane = threadIdx.x & 31;
    const int wid = (blockIdx.x * blockDim.x + threadIdx.x) >> 5;
    const int nWarps = (gridDim.x * blockDim.x) >> 5;
    for (int w = wid; w < NROWS * 256; w += nWarps) {
        int v = adj[(size_t)w * 32 + lane];
        unsigned b = __ballot_sync(0xffffffffu, v > 0);
        if (lane == 0) g_mask[w] = b;
    }
}

// ---------------- 2) h = x @ Wh[head] (8192x512x64) ----------------
__global__ void __launch_bounds__(256) gemm64_kernel(const float* __restrict__ X,
                                                     const float* __restrict__ WhAll) {
    const int head = blockIdx.y;
    const float* W = WhAll + head * (512 * 64);
    float* C = g_h + head * (NROWS * 64);
    const int r0 = blockIdx.x * 64;
    const int tid = threadIdx.x;
    __shared__ float4 As4[512];  // [32 k][64 m]
    __shared__ float4 Bs4[512];  // [32 k][64 n]
    float* As = (float*)As4;
    const int tr = tid >> 4, tc = tid & 15;
    const int lm = tid & 63, kg = tid >> 6;
    float acc[4][4];
#pragma unroll
    for (int i = 0; i < 4; i++)
#pragma unroll
        for (int j = 0; j < 4; j++) acc[i][j] = 0.f;

    for (int kt = 0; kt < 512; kt += 32) {
        __syncthreads();
        const float* xb = X + (size_t)(r0 + lm) * 512 + kt + kg * 8;
        float4 a0 = ((const float4*)xb)[0];
        float4 a1 = ((const float4*)xb)[1];
        As[(kg * 8 + 0) * 64 + lm] = a0.x; As[(kg * 8 + 1) * 64 + lm] = a0.y;
        As[(kg * 8 + 2) * 64 + lm] = a0.z; As[(kg * 8 + 3) * 64 + lm] = a0.w;
        As[(kg * 8 + 4) * 64 + lm] = a1.x; As[(kg * 8 + 5) * 64 + lm] = a1.y;
        As[(kg * 8 + 6) * 64 + lm] = a1.z; As[(kg * 8 + 7) * 64 + lm] = a1.w;
        const float4* wsrc = (const float4*)(W + kt * 64);
        Bs4[tid] = wsrc[tid];
        Bs4[tid + 256] = wsrc[tid + 256];
        __syncthreads();
#pragma unroll
        for (int kk = 0; kk < 32; kk++) {
            float4 av = As4[kk * 16 + tr];
            float4 bv = Bs4[kk * 16 + tc];
            float aa[4] = {av.x, av.y, av.z, av.w};
            float bb[4] = {bv.x, bv.y, bv.z, bv.w};
#pragma unroll
            for (int i = 0; i < 4; i++)
#pragma unroll
                for (int j = 0; j < 4; j++) acc[i][j] += aa[i] * bb[j];
        }
    }
#pragma unroll
    for (int i = 0; i < 4; i++) {
        float4 o = make_float4(acc[i][0], acc[i][1], acc[i][2], acc[i][3]);
        *(float4*)(C + (size_t)(r0 + tr * 4 + i) * 64 + tc * 4) = o;
    }
}

// ---------------- 3) f1/f2 (log2-scaled) ----------------
__global__ void __launch_bounds__(256) f1f2_heads_kernel(const float* __restrict__ ah) {
    const int head = blockIdx.y;
    const float* H = g_h + head * (NROWS * 64);
    const float* a = ah + head * 128;
    const int lane = threadIdx.x & 31;
    const int row = blockIdx.x * 8 + (threadIdx.x >> 5);
    float h0 = H[row * 64 + lane], h1 = H[row * 64 + 32 + lane];
    float s1 = h0 * a[lane] + h1 * a[32 + lane];
    float s2 = h0 * a[64 + lane] + h1 * a[96 + lane];
#pragma unroll
    for (int off = 16; off; off >>= 1) {
        s1 += __shfl_xor_sync(0xffffffffu, s1, off);
        s2 += __shfl_xor_sync(0xffffffffu, s2, off);
    }
    if (lane == 0) {
        g_f1[head * NROWS + row] = s1 * L2E;
        g_f2[head * NROWS + row] = s2 * L2E;
    }
}

__global__ void __launch_bounds__(256) f1f2_final_kernel(const float* __restrict__ ao) {
    const int lane = threadIdx.x & 31;
    const int row = blockIdx.x * 8 + (threadIdx.x >> 5);
    float s1 = 0.f, s2 = 0.f;
    if (lane < 16) {
        float h = g_h2[row * 16 + lane];
        s1 = h * ao[lane];
        s2 = h * ao[16 + lane];
    }
#pragma unroll
    for (int off = 16; off; off >>= 1) {
        s1 += __shfl_xor_sync(0xffffffffu, s1, off);
        s2 += __shfl_xor_sync(0xffffffffu, s2, off);
    }
    if (lane == 0) {
        g_f1[4 * NROWS + row] = s1 * L2E;
        g_f2[4 * NROWS + row] = s2 * L2E;
    }
}

// ---------------- 3b) B values per column ----------------
__global__ void __launch_bounds__(256) bvals_kernel(int layer0) {
    const int layer = layer0 + blockIdx.y;
    const int j = blockIdx.x * 256 + threadIdx.x;
    float f2 = g_f2[layer * NROWS + j];
    g_fb4[layer * NROWS + j] = make_float4(f2, ex2f(f2), ex2f(0.2f * f2), 0.f);
}

// ---------------- 4a) masked row max + A values, 4 heads ----------------
__global__ void __launch_bounds__(256) rowmax4_kernel() {
    const int lane = threadIdx.x & 31;
    const int row = blockIdx.x * 8 + (threadIdx.x >> 5);
    const int sh = (lane & 7) * 4;
    float mx0 = -3.0e38f, mx1 = -3.0e38f, mx2 = -3.0e38f, mx3 = -3.0e38f;
    for (int jb = 0; jb < NROWS; jb += 128) {
        uint4 mw = *(const uint4*)&g_mask[row * 256 + (jb >> 5)];
        unsigned word = (lane < 8) ? mw.x : (lane < 16) ? mw.y : (lane < 24) ? mw.z : mw.w;
        const int j = jb + lane * 4;
        float4 v0 = *(const float4*)&g_f2[0 * NROWS + j];
        float4 v1 = *(const float4*)&g_f2[1 * NROWS + j];
        float4 v2 = *(const float4*)&g_f2[2 * NROWS + j];
        float4 v3 = *(const float4*)&g_f2[3 * NROWS + j];
#pragma unroll
        for (int i = 0; i < 4; i++) {
            bool on = (word >> (sh + i)) & 1u;
            mx0 = fmaxf(mx0, on ? ((const float*)&v0)[i] : -3.0e38f);
            mx1 = fmaxf(mx1, on ? ((const float*)&v1)[i] : -3.0e38f);
            mx2 = fmaxf(mx2, on ? ((const float*)&v2)[i] : -3.0e38f);
            mx3 = fmaxf(mx3, on ? ((const float*)&v3)[i] : -3.0e38f);
        }
    }
#pragma unroll
    for (int off = 16; off; off >>= 1) {
        mx0 = fmaxf(mx0, __shfl_xor_sync(0xffffffffu, mx0, off));
        mx1 = fmaxf(mx1, __shfl_xor_sync(0xffffffffu, mx1, off));
        mx2 = fmaxf(mx2, __shfl_xor_sync(0xffffffffu, mx2, off));
        mx3 = fmaxf(mx3, __shfl_xor_sync(0xffffffffu, mx3, off));
    }
    if (lane == 0) {
        float mx[4] = {mx0, mx1, mx2, mx3};
#pragma unroll
        for (int hd = 0; hd < 4; hd++) {
            float f1v = g_f1[hd * NROWS + row];
            float s = f1v + mx[hd];
            float m = fmaxf(s, 0.2f * s);
            g_a[hd * NROWS + row] = make_float2(ex2f(f1v - m), ex2f(0.2f * f1v - m));
        }
    }
}

// ---------------- 4b) masked row max + A values, final layer ----------------
__global__ void __launch_bounds__(256) rowmax1_kernel() {
    const int lane = threadIdx.x & 31;
    const int row = blockIdx.x * 8 + (threadIdx.x >> 5);
    const int sh = (lane & 7) * 4;
    const float* __restrict__ f2 = g_f2 + 4 * NROWS;
    float mx = -3.0e38f;
    for (int jb = 0; jb < NROWS; jb += 128) {
        uint4 mw = *(const uint4*)&g_mask[row * 256 + (jb >> 5)];
        unsigned word = (lane < 8) ? mw.x : (lane < 16) ? mw.y : (lane < 24) ? mw.z : mw.w;
        float4 v = *(const float4*)&f2[jb + lane * 4];
#pragma unroll
        for (int i = 0; i < 4; i++) {
            bool on = (word >> (sh + i)) & 1u;
            mx = fmaxf(mx, on ? ((const float*)&v)[i] : -3.0e38f);
        }
    }
#pragma unroll
    for (int off = 16; off; off >>= 1) mx = fmaxf(mx, __shfl_xor_sync(0xffffffffu, mx, off));
    if (lane == 0) {
        float f1v = g_f1[4 * NROWS + row];
        float s = f1v + mx;
        float m = fmaxf(s, 0.2f * s);
        g_a[4 * NROWS + row] = make_float2(ex2f(f1v - m), ex2f(0.2f * f1v - m));
    }
}

// ---------------- 5) head attention as tiled GEMM over materialized P ----------
// block: 128 thr; computes rows r0..r0+127 x 64 cols for (head, jsplit of 2048 j)
// thread tile: 8 rows x 8 cols. P chunk 32 j materialized in smem (stride 132).
#define PSTRIDE 132
__global__ void __launch_bounds__(128) attn_heads_gemm() {
    const int head = blockIdx.y;
    const int split = blockIdx.z;
    const int r0 = blockIdx.x * 128;
    const int tid = threadIdx.x;
    const int tr = tid >> 3;          // 0..15 -> rows tr*8..+7
    const int tc = tid & 7;           // 0..7  -> cols tc*8..+7
    const int jj = tid & 31;          // P-build column
    const int quarter = tid >> 5;     // P-build row quarter

    __shared__ float Ps[32 * PSTRIDE];   // [jj][i], padded
    __shared__ float Hs[32 * 64];        // [jj][c]
    __shared__ float f1s[128], Aps[128], Ams[128];
    __shared__ unsigned mws[128];

    if (tid < 128) {
        f1s[tid] = g_f1[head * NROWS + r0 + tid];
        float2 av = g_a[head * NROWS + r0 + tid];
        Aps[tid] = av.x; Ams[tid] = av.y;
    }

    unsigned long long acc[8][4];
#pragma unroll
    for (int r = 0; r < 8; r++)
#pragma unroll
        for (int c = 0; c < 4; c++) acc[r][c] = 0ull;
    float zrow = 0.f;

    const int jbase = split * 2048;
    for (int ch = 0; ch < 64; ch++) {
        const int j0 = jbase + ch * 32;
        __syncthreads();
        // stage H chunk: 32x64 floats
        {
            const float4* src = (const float4*)(g_h + (size_t)head * NROWS * 64 + (size_t)j0 * 64);
            float4* dst = (float4*)Hs;
#pragma unroll
            for (int v = 0; v < 4; v++) dst[tid + 128 * v] = src[tid + 128 * v];
        }
        // stage mask words (1 word per row for 32 j)
        mws[tid] = g_mask[(size_t)(r0 + tid) * 256 + (j0 >> 5)];
        // own-j B values
        float4 fb = g_fb4[head * NROWS + j0 + jj];
        const float f2r = fb.x, Bpr = fb.y, Bmr = fb.z;
        __syncthreads();
        // build P chunk: thread owns column jj, rows quarter*32..+31
        {
            const int i0 = quarter * 32;
            float* prow = Ps + jj * PSTRIDE;
#pragma unroll
            for (int ib = 0; ib < 32; ib += 4) {
                float pv[4];
#pragma unroll
                for (int ii = 0; ii < 4; ii++) {
                    const int i = i0 + ib + ii;
                    float s = f1s[i] + f2r;
                    bool pos = s >= 0.f;
                    float a = pos ? Aps[i] : Ams[i];
                    float b = pos ? Bpr : Bmr;
                    pv[ii] = ((mws[i] >> jj) & 1u) ? a * b : 0.f;
                }
                *(float4*)(prow + i0 + ib) = make_float4(pv[0], pv[1], pv[2], pv[3]);
            }
        }
        __syncthreads();
        // k-loop: 32 j
#pragma unroll 2
        for (int k = 0; k < 32; k++) {
            float4 pa = *(const float4*)(Ps + k * PSTRIDE + tr * 8);
            float4 pb = *(const float4*)(Ps + k * PSTRIDE + tr * 8 + 4);
            unsigned long long h0, h1, h2, h3;
            lds2u64(Hs + k * 64 + tc * 8, h0, h1);
            lds2u64(Hs + k * 64 + tc * 8 + 4, h2, h3);
            unsigned long long p2[8];
            p2[0] = pk2(pa.x, pa.x); p2[1] = pk2(pa.y, pa.y);
            p2[2] = pk2(pa.z, pa.z); p2[3] = pk2(pa.w, pa.w);
            p2[4] = pk2(pb.x, pb.x); p2[5] = pk2(pb.y, pb.y);
            p2[6] = pk2(pb.z, pb.z); p2[7] = pk2(pb.w, pb.w);
#pragma unroll
            for (int r = 0; r < 8; r++) {
                fma2(acc[r][0], p2[r], h0);
                fma2(acc[r][1], p2[r], h1);
                fma2(acc[r][2], p2[r], h2);
                fma2(acc[r][3], p2[r], h3);
            }
        }
        // z pass: thread sums column tid of P
        {
            float zs = 0.f;
#pragma unroll 8
            for (int k = 0; k < 32; k++) zs += Ps[k * PSTRIDE + tid];
            zrow += zs;
        }
    }
    // epilogue
    const int base = (split * 4 + head) * NROWS;
#pragma unroll
    for (int r = 0; r < 8; r++) {
        const int row = r0 + tr * 8 + r;
        float v[8];
        up2(acc[r][0], v[0], v[1]);
        up2(acc[r][1], v[2], v[3]);
        up2(acc[r][2], v[4], v[5]);
        up2(acc[r][3], v[6], v[7]);
        float* op = g_hp + ((size_t)base + row) * 64 + tc * 8;
        *(float4*)op = make_float4(v[0], v[1], v[2], v[3]);
        *(float4*)(op + 4) = make_float4(v[4], v[5], v[6], v[7]);
    }
    g_hpZ[base + r0 + tid] = zrow;
}

// ---------------- 5b) reduce head partials -> xcat (with LR 0.01) ----------------
__global__ void __launch_bounds__(256) reduce_heads_kernel() {
    const int idx = blockIdx.x * 256 + threadIdx.x;  // 8192*256
    const int row = idx >> 8;
    const int cc = idx & 255;
    const int head = cc >> 6;
    const int col = cc & 63;
    float s = 0.f, z = 0.f;
#pragma unroll
    for (int sp = 0; sp < 4; sp++) {
        s += g_hp[((size_t)(sp * 4 + head) * NROWS + row) * 64 + col];
        z += g_hpZ[(sp * 4 + head) * NROWS + row];
    }
    float v = s / z;
    g_xcat[(size_t)row * 256 + cc] = fmaxf(v, 0.01f * v);
}

// ---------------- 6) h2 = xcat @ Wo (8192x256x16) ----------------
__global__ void __launch_bounds__(128) gemm2_kernel(const float* __restrict__ Wo) {
    __shared__ float Ws[256 * 16];
    const int tid = threadIdx.x;
    for (int i = tid; i < 4096; i += 128) Ws[i] = Wo[i];
    __syncthreads();
    const int row = blockIdx.x * 128 + tid;
    const float* xr = g_xcat + (size_t)row * 256;
    float acc[16];
#pragma unroll
    for (int j = 0; j < 16; j++) acc[j] = 0.f;
    for (int k = 0; k < 256; k += 4) {
        float4 xv = *(const float4*)(xr + k);
#pragma unroll
        for (int j = 0; j < 16; j++) {
            acc[j] += xv.x * Ws[(k + 0) * 16 + j];
            acc[j] += xv.y * Ws[(k + 1) * 16 + j];
            acc[j] += xv.z * Ws[(k + 2) * 16 + j];
            acc[j] += xv.w * Ws[(k + 3) * 16 + j];
        }
    }
#pragma unroll
    for (int j = 0; j < 16; j++) g_h2[row * 16 + j] = acc[j];
}

// ---------------- 7) final attention as tiled GEMM (16 cols) ----------------
// block 128 thr: rows r0..+127 x 16 cols, jsplit of 1024. thread tile 8 rows x 2 cols.
__global__ void __launch_bounds__(128) attn_final_gemm() {
    const int split = blockIdx.y;  // 0..7
    const int r0 = blockIdx.x * 128;
    const int tid = threadIdx.x;
    const int tr = tid >> 3;       // 0..15 -> rows tr*8..+7
    const int tc = tid & 7;        // colpair -> cols 2tc, 2tc+1
    const int jj = tid & 31;
    const int quarter = tid >> 5;

    __shared__ float Ps[32 * PSTRIDE];
    __shared__ float Hs[32 * 16];
    __shared__ float f1s[128], Aps[128], Ams[128];
    __shared__ unsigned mws[128];

    if (tid < 128) {
        f1s[tid] = g_f1[4 * NROWS + r0 + tid];
        float2 av = g_a[4 * NROWS + r0 + tid];
        Aps[tid] = av.x; Ams[tid] = av.y;
    }

    unsigned long long acc[8];
#pragma unroll
    for (int r = 0; r < 8; r++) acc[r] = 0ull;
    float zrow = 0.f;

    const int jbase = split * 1024;
    for (int ch = 0; ch < 32; ch++) {
        const int j0 = jbase + ch * 32;
        __syncthreads();
        {
            const float4* src = (const float4*)(g_h2 + (size_t)j0 * 16);
            if (tid < 128) ((float4*)Hs)[tid] = src[tid];
        }
        mws[tid] = g_mask[(size_t)(r0 + tid) * 256 + (j0 >> 5)];
        float4 fb = g_fb4[4 * NROWS + j0 + jj];
        const float f2r = fb.x, Bpr = fb.y, Bmr = fb.z;
        __syncthreads();
        {
            const int i0 = quarter * 32;
            float* prow = Ps + jj * PSTRIDE;
#pragma unroll
            for (int ib = 0; ib < 32; ib += 4) {
                float pv[4];
#pragma unroll
                for (int ii = 0; ii < 4; ii++) {
                    const int i = i0 + ib + ii;
                    float s = f1s[i] + f2r;
                    bool pos = s >= 0.f;
                    float a = pos ? Aps[i] : Ams[i];
                    float b = pos ? Bpr : Bmr;
                    pv[ii] = ((mws[i] >> jj) & 1u) ? a * b : 0.f;
                }
                *(float4*)(prow + i0 + ib) = make_float4(pv[0], pv[1], pv[2], pv[3]);
            }
        }
        __syncthreads();
#pragma unroll 2
        for (int k = 0; k < 32; k++) {
            float4 pa = *(const float4*)(Ps + k * PSTRIDE + tr * 8);
            float4 pb = *(const float4*)(Ps + k * PSTRIDE + tr * 8 + 4);
            unsigned long long h0 = lds1u64(Hs + k * 16 + tc * 2);
            unsigned long long p2[8];
            p2[0] = pk2(pa.x, pa.x); p2[1] = pk2(pa.y, pa.y);
            p2[2] = pk2(pa.z, pa.z); p2[3] = pk2(pa.w, pa.w);
            p2[4] = pk2(pb.x, pb.x); p2[5] = pk2(pb.y, pb.y);
            p2[6] = pk2(pb.z, pb.z); p2[7] = pk2(pb.w, pb.w);
#pragma unroll
            for (int r = 0; r < 8; r++) fma2(acc[r], p2[r], h0);
        }
        {
            float zs = 0.f;
#pragma unroll 8
            for (int k = 0; k < 32; k++) zs += Ps[k * PSTRIDE + tid];
            zrow += zs;
        }
    }
#pragma unroll
    for (int r = 0; r < 8; r++) {
        const int row = r0 + tr * 8 + r;
        *(unsigned long long*)&g_part[((size_t)split * NROWS + row) * 16 + tc * 2] = acc[r];
    }
    g_partZ[split * NROWS + r0 + tid] = zrow;
}

// ---------------- 8) reduce partials -> output ----------------
__global__ void __launch_bounds__(256) reduce_kernel(float* __restrict__ out) {
    const int idx = blockIdx.x * 256 + threadIdx.x;  // 8192*16
    const int row = idx >> 4;
    float s = 0.f, z = 0.f;
#pragma unroll
    for (int c = 0; c < 8; c++) {
        s += g_part[((size_t)c * NROWS + row) * 16 + (idx & 15)];
        z += g_partZ[c * NROWS + row];
    }
    out[idx] = s / z;
}

extern "C" void kernel_launch(void* const* d_in, const int* in_sizes, int n_in,
                              void* d_out, int out_size) {
    const float* x   = (const float*)d_in[0];
    const int*   adj = (const int*)d_in[1];
    const float* Wh  = (const float*)d_in[2];
    const float* ah  = (const float*)d_in[3];
    const float* Wo  = (const float*)d_in[4];
    const float* ao  = (const float*)d_in[5];
    float* out = (float*)d_out;

    pack_adj_kernel<<<2048, 256>>>(adj);
    gemm64_kernel<<<dim3(128, 4), 256>>>(x, Wh);
    f1f2_heads_kernel<<<dim3(1024, 4), 256>>>(ah);
    bvals_kernel<<<dim3(32, 4), 256>>>(0);
    rowmax4_kernel<<<1024, 256>>>();
    attn_heads_gemm<<<dim3(64, 4, 4), 128>>>();
    reduce_heads_kernel<<<8192, 256>>>();
    gemm2_kernel<<<64, 128>>>(Wo);
    f1f2_final_kernel<<<1024, 256>>>(ao);
    bvals_kernel<<<dim3(32, 1), 256>>>(4);
    rowmax1_kernel<<<1024, 256>>>();
    attn_final_gemm<<<dim3(64, 8), 128>>>();
    reduce_kernel<<<512, 256>>>(out);
}